// round 16
// baseline (speedup 1.0000x reference)
#include <cuda_runtime.h>
#include <cuda_fp16.h>
#include <mma.h>
#include <cstdint>

using namespace nvcuda;

#define NPTS 8192
#define DDIM 512
#define ODIM 512

static constexpr float INV2SIG2 = 1.0f / 2048.0f;   // 1/(2*32*32)
static constexpr float EPSV = 1e-8f;

// ---------------- scratch ----------------
__device__ __half g_x[(size_t)NPTS * DDIM];      // fp16 x [N][D]
__device__ __half g_W[(size_t)ODIM * DDIM];      // fp16 W [O][D]
__device__ __half g_P[(size_t)NPTS * NPTS];      // fp16 weights, 128 MB
__device__ __half g_Y[(size_t)NPTS * DDIM];      // fp16 normalized P@x
__device__ float  g_sq[NPTS];
__device__ float  g_invr[NPTS];
__device__ float  g_part[(size_t)64 * NPTS];     // per-sumblock row partials (2 MB)

// ---------------- cp.async ----------------
__device__ __forceinline__ void cp16s(unsigned dst, const void* src) {
    asm volatile("cp.async.cg.shared.global [%0], [%1], 16;" :: "r"(dst), "l"(src));
}
#define CP_COMMIT() asm volatile("cp.async.commit_group;" ::: "memory")
#define CP_WAIT1()  asm volatile("cp.async.wait_group 1;" ::: "memory")
#define CP_WAIT0()  asm volatile("cp.async.wait_group 0;" ::: "memory")

__device__ __forceinline__ unsigned smem_u32(const void* p) {
    return (unsigned)__cvta_generic_to_shared(p);
}

// geometry: BM=128, BN=128, BK=64
#define A_ROW_H   72
#define A_BYTES   18432
#define STAGE_B   36864
#define GRAM_DYN  (3 * STAGE_B)
#define PV_DYN    (3 * STAGE_B)
#define HEAD_DYN  (2 * STAGE_B)
// gram epilogue aliases:
#define TT_OFF    0
#define PATCH_OFF (2 * STAGE_B)
#define COLP_OFF  (2 * STAGE_B + 10240)

// ---------------- prep kernels ----------------
__global__ void k_prep_x(const float* __restrict__ x) {
    int row = blockIdx.x * 8 + (threadIdx.x >> 5);
    int lane = threadIdx.x & 31;
    const float4* xr = (const float4*)(x + (size_t)row * DDIM);
    float s = 0.f;
    #pragma unroll
    for (int i = lane; i < 128; i += 32) {
        float4 v = xr[i];
        s += v.x * v.x + v.y * v.y + v.z * v.z + v.w * v.w;
        __half2* dst = (__half2*)(g_x + (size_t)row * DDIM + i * 4);
        dst[0] = __floats2half2_rn(v.x, v.y);
        dst[1] = __floats2half2_rn(v.z, v.w);
    }
    #pragma unroll
    for (int o = 16; o > 0; o >>= 1) s += __shfl_xor_sync(0xffffffff, s, o);
    if (lane == 0) g_sq[row] = s;
}

__global__ void k_prep_w(const float* __restrict__ W) {
    int i = blockIdx.x * blockDim.x + threadIdx.x;
    float4 v = ((const float4*)W)[i];
    __half2* dst = (__half2*)(g_W + (size_t)i * 4);
    dst[0] = __floats2half2_rn(v.x, v.y);
    dst[1] = __floats2half2_rn(v.z, v.w);
}

// ---------------- K2: symmetric Gram -> exp -> P (R15, measured ~champion) ----------------
__global__ void __launch_bounds__(256) k_gauss() {
    extern __shared__ __align__(16) char dyn[];
    __shared__ float sqj[128];
    __shared__ float part2[2][128];

    int bx = blockIdx.x, by = blockIdx.y;
    int ib, jb;
    if (bx >= by) { ib = by; jb = bx; }
    else {
        if (by == 32) return;
        ib = 64 - by; jb = 63 - bx;
    }
    bool diag = (jb == ib);

    unsigned sb = smem_u32(dyn);
    __half* Hs = (__half*)dyn;

    int i0 = ib * 128;
    int j0 = jb * 128;
    int tid = threadIdx.x, warp = tid >> 5, lane = tid & 31;
    int wm = warp >> 1;
    int wn = warp & 1;

    if (tid < 128) sqj[tid] = g_sq[j0 + tid];

    wmma::fragment<wmma::accumulator, 16, 16, 16, float> acc[2][4];
    #pragma unroll
    for (int a = 0; a < 2; a++)
        #pragma unroll
        for (int b = 0; b < 4; b++) wmma::fill_fragment(acc[a][b], 0.f);

    auto load_chunk = [&](int c, int st) {
        unsigned ab = sb + st * STAGE_B;
        unsigned bb = ab + A_BYTES;
        const __half* ga = g_x + (size_t)i0 * DDIM + c * 64;
        const __half* gb = g_x + (size_t)j0 * DDIM + c * 64;
        #pragma unroll
        for (int q = 0; q < 4; q++) {
            int idx = tid + q * 256;
            int r = idx >> 3, g = idx & 7;
            cp16s(ab + r * 144 + g * 16, ga + (size_t)r * DDIM + g * 8);
        }
        #pragma unroll
        for (int q = 0; q < 4; q++) {
            int idx = tid + q * 256;
            int r = idx >> 3, g = idx & 7;
            cp16s(bb + r * 144 + g * 16, gb + (size_t)r * DDIM + g * 8);
        }
        CP_COMMIT();
    };

    load_chunk(0, 0);
    load_chunk(1, 1);

    int st = 0;
    for (int s = 0; s < 8; s++) {
        if (s < 7) CP_WAIT1(); else CP_WAIT0();
        __syncthreads();
        if (s + 2 < 8) {
            int st2 = st + 2; if (st2 >= 3) st2 -= 3;
            load_chunk(s + 2, st2);
        }
        __half* A = Hs + st * (STAGE_B / 2);
        __half* B = A + A_BYTES / 2;
        #pragma unroll
        for (int kc = 0; kc < 4; kc++) {
            wmma::fragment<wmma::matrix_a, 16, 16, 16, __half, wmma::row_major> af[2];
            #pragma unroll
            for (int mi = 0; mi < 2; mi++)
                wmma::load_matrix_sync(af[mi], A + (wm * 32 + mi * 16) * A_ROW_H + kc * 16, A_ROW_H);
            #pragma unroll
            for (int ni = 0; ni < 4; ni++) {
                wmma::fragment<wmma::matrix_b, 16, 16, 16, __half, wmma::col_major> bf;
                wmma::load_matrix_sync(bf, B + (wn * 64 + ni * 16) * A_ROW_H + kc * 16, A_ROW_H);
                wmma::mma_sync(acc[0][ni], af[0], bf, acc[0][ni]);
                wmma::mma_sync(acc[1][ni], af[1], bf, acc[1][ni]);
            }
        }
        if (++st >= 3) st = 0;
    }

    __half* Tt   = (__half*)(dyn + TT_OFF);
    float* patch = (float*)(dyn + PATCH_OFF) + warp * 320;
    float* colp  = (float*)(dyn + COLP_OFF);
    int rr = lane >> 1;
    int cc0 = (lane & 1) * 8;
    float colacc[4][8];
    #pragma unroll
    for (int a = 0; a < 4; a++)
        #pragma unroll
        for (int e = 0; e < 8; e++) colacc[a][e] = 0.f;

    #pragma unroll
    for (int mi = 0; mi < 2; mi++) {
        int row_loc = wm * 32 + mi * 16 + rr;
        int gi = i0 + row_loc;
        float si = g_sq[gi];
        float s = 0.f;
        #pragma unroll
        for (int ni = 0; ni < 4; ni++) {
            wmma::store_matrix_sync(patch, acc[mi][ni], 20, wmma::mem_row_major);
            __syncwarp();
            int jl = wn * 64 + ni * 16 + cc0;
            __half2 buf2[4];
            #pragma unroll
            for (int e = 0; e < 8; e += 2) {
                float d0 = fmaxf(si + sqj[jl + e]     - 2.f * patch[rr * 20 + cc0 + e],     0.f);
                float d1 = fmaxf(si + sqj[jl + e + 1] - 2.f * patch[rr * 20 + cc0 + e + 1], 0.f);
                __half2 hp = __floats2half2_rn(__expf(-d0 * INV2SIG2), __expf(-d1 * INV2SIG2));
                buf2[e >> 1] = hp;
                float2 hf = __half22float2(hp);
                s += hf.x + hf.y;
                if (!diag) {
                    colacc[ni][e]     += hf.x;
                    colacc[ni][e + 1] += hf.y;
                    Tt[(jl + e)     * 136 + row_loc] = __low2half(hp);
                    Tt[(jl + e + 1) * 136 + row_loc] = __high2half(hp);
                }
            }
            *(uint4*)(g_P + (size_t)gi * NPTS + j0 + jl) = *(const uint4*)buf2;
            __syncwarp();
        }
        s += __shfl_xor_sync(0xffffffff, s, 1);
        if ((lane & 1) == 0) part2[wn][row_loc] = s;
    }

    if (!diag) {
        #pragma unroll
        for (int ni = 0; ni < 4; ni++)
            #pragma unroll
            for (int e = 0; e < 8; e++) {
                float v = colacc[ni][e];
                v += __shfl_xor_sync(0xffffffff, v, 2);
                v += __shfl_xor_sync(0xffffffff, v, 4);
                v += __shfl_xor_sync(0xffffffff, v, 8);
                v += __shfl_xor_sync(0xffffffff, v, 16);
                colacc[ni][e] = v;
            }
        if (rr == 0) {
            #pragma unroll
            for (int ni = 0; ni < 4; ni++)
                #pragma unroll
                for (int e = 0; e < 8; e++)
                    colp[wm * 128 + wn * 64 + ni * 16 + cc0 + e] = colacc[ni][e];
        }
    }
    __syncthreads();

    if (tid < 128) {
        g_part[(size_t)jb * NPTS + i0 + tid] = part2[0][tid] + part2[1][tid];
        if (!diag)
            g_part[(size_t)ib * NPTS + j0 + tid] =
                (colp[tid] + colp[128 + tid]) + (colp[256 + tid] + colp[384 + tid]);
    }

    if (!diag) {
        int jc = tid >> 1, ih = tid & 1;
        const uint4* src = (const uint4*)(Tt + jc * 136 + ih * 64);
        uint4* dst = (uint4*)(g_P + (size_t)(j0 + jc) * NPTS + i0 + ih * 64);
        #pragma unroll
        for (int q = 0; q < 8; q++) dst[q] = src[q];
    }
}

// ---------------- K2.5 ----------------
__global__ void k_rowsum() {
    int row = blockIdx.x * 256 + threadIdx.x;
    float s = 0.f;
    #pragma unroll
    for (int jt = 0; jt < 64; jt++) s += g_part[(size_t)jt * NPTS + row];
    g_invr[row] = 1.f / (s + EPSV);
}

// ---------------- K3: Y = (P @ x) * invr. 4 warps, 64x64 warp tile, 3 CTA/SM ----------------
#define PVB_ROW_H 136
__global__ void __launch_bounds__(128, 3) k_pv() {
    extern __shared__ __align__(16) char dyn[];
    unsigned sb = smem_u32(dyn);
    __half* Hs = (__half*)dyn;

    int i0 = blockIdx.y * 128;
    int n0 = blockIdx.x * 128;
    int tid = threadIdx.x, warp = tid >> 5, lane = tid & 31;
    int wm = warp >> 1;   // 0..1
    int wn = warp & 1;    // 0..1

    wmma::fragment<wmma::accumulator, 16, 16, 16, float> acc[4][4];
    #pragma unroll
    for (int a = 0; a < 4; a++)
        #pragma unroll
        for (int b = 0; b < 4; b++) wmma::fill_fragment(acc[a][b], 0.f);

    auto load_chunk = [&](int c, int st) {
        unsigned ab = sb + st * STAGE_B;
        unsigned bb = ab + A_BYTES;
        const __half* ga = g_P + (size_t)i0 * NPTS + c * 64;
        const __half* gb = g_x + (size_t)(c * 64) * DDIM + n0;
        #pragma unroll
        for (int q = 0; q < 8; q++) {          // A: 1024 granules / 128 thr
            int idx = tid + q * 128;
            int r = idx >> 3, g = idx & 7;
            cp16s(ab + r * 144 + g * 16, ga + (size_t)r * NPTS + g * 8);
        }
        #pragma unroll
        for (int q = 0; q < 8; q++) {          // B: 1024 granules
            int idx = tid + q * 128;
            int r = idx >> 4, g = idx & 15;
            cp16s(bb + r * 272 + g * 16, gb + (size_t)r * DDIM + g * 8);
        }
        CP_COMMIT();
    };

    load_chunk(0, 0);
    load_chunk(1, 1);

    int st = 0;
    for (int s = 0; s < 128; s++) {
        if (s < 127) CP_WAIT1(); else CP_WAIT0();
        __syncthreads();
        if (s + 2 < 128) {
            int st2 = st + 2; if (st2 >= 3) st2 -= 3;
            load_chunk(s + 2, st2);
        }
        __half* A = Hs + st * (STAGE_B / 2);
        __half* B = A + A_BYTES / 2;
        #pragma unroll
        for (int kc = 0; kc < 4; kc++) {
            wmma::fragment<wmma::matrix_a, 16, 16, 16, __half, wmma::row_major> af[4];
            #pragma unroll
            for (int mi = 0; mi < 4; mi++)
                wmma::load_matrix_sync(af[mi], A + (wm * 64 + mi * 16) * A_ROW_H + kc * 16, A_ROW_H);
            #pragma unroll
            for (int ni = 0; ni < 4; ni++) {
                wmma::fragment<wmma::matrix_b, 16, 16, 16, __half, wmma::row_major> bf;
                wmma::load_matrix_sync(bf, B + (kc * 16) * PVB_ROW_H + wn * 64 + ni * 16, PVB_ROW_H);
                #pragma unroll
                for (int mi = 0; mi < 4; mi++)
                    wmma::mma_sync(acc[mi][ni], af[mi], bf, acc[mi][ni]);
            }
        }
        if (++st >= 3) st = 0;
    }

    // epilogue: per-warp patch in stage-0 region (stage 0 last used by chunk 126; barrier at
    // s=127 top proves all warps finished it; chunk 127 compute reads stage 1 only)
    float* patch = (float*)dyn + warp * 320;
    int rr = lane >> 1;
    int cc0 = (lane & 1) * 8;
    #pragma unroll
    for (int mi = 0; mi < 4; mi++) {
        int gi = i0 + wm * 64 + mi * 16 + rr;
        float inv = g_invr[gi];
        #pragma unroll
        for (int ni = 0; ni < 4; ni++) {
            wmma::store_matrix_sync(patch, acc[mi][ni], 20, wmma::mem_row_major);
            __syncwarp();
            int nl = wn * 64 + ni * 16 + cc0;
            __half2 buf2[4];
            #pragma unroll
            for (int e = 0; e < 8; e += 2)
                buf2[e >> 1] = __floats2half2_rn(patch[rr * 20 + cc0 + e] * inv,
                                                 patch[rr * 20 + cc0 + e + 1] * inv);
            *(uint4*)(g_Y + (size_t)gi * DDIM + n0 + nl) = *(const uint4*)buf2;
            __syncwarp();
        }
    }
}

// ---------------- K4: out = Y @ W^T + b. 128x128 tile, K=512 ----------------
__global__ void __launch_bounds__(256) k_head(const float* __restrict__ bvec,
                                              float* __restrict__ out) {
    extern __shared__ __align__(16) char dyn[];
    __shared__ float bs[128];
    unsigned sb = smem_u32(dyn);
    __half* Hs = (__half*)dyn;

    int i0 = blockIdx.y * 128;
    int n0 = blockIdx.x * 128;
    int tid = threadIdx.x, warp = tid >> 5, lane = tid & 31;
    int wm = warp >> 1;
    int wn = warp & 1;

    if (tid < 128) bs[tid] = bvec[n0 + tid];

    wmma::fragment<wmma::accumulator, 16, 16, 16, float> acc[2][4];
    #pragma unroll
    for (int a = 0; a < 2; a++)
        #pragma unroll
        for (int b = 0; b < 4; b++) wmma::fill_fragment(acc[a][b], 0.f);

    auto load_chunk = [&](int c, int st) {
        unsigned ab = sb + st * STAGE_B;
        unsigned bb = ab + A_BYTES;
        const __half* ga = g_Y + (size_t)i0 * DDIM + c * 64;
        const __half* gb = g_W + (size_t)n0 * DDIM + c * 64;
        #pragma unroll
        for (int q = 0; q < 4; q++) {
            int idx = tid + q * 256;
            int r = idx >> 3, g = idx & 7;
            cp16s(ab + r * 144 + g * 16, ga + (size_t)r * DDIM + g * 8);
        }
        #pragma unroll
        for (int q = 0; q < 4; q++) {
            int idx = tid + q * 256;
            int r = idx >> 3, g = idx & 7;
            cp16s(bb + r * 144 + g * 16, gb + (size_t)r * DDIM + g * 8);
        }
        CP_COMMIT();
    };

    load_chunk(0, 0);
    for (int s = 0; s < 8; s++) {
        int buf = s & 1;
        if (s < 7) { load_chunk(s + 1, buf ^ 1); CP_WAIT1(); } else { CP_WAIT0(); }
        __syncthreads();
        __half* A = Hs + buf * (STAGE_B / 2);
        __half* B = A + A_BYTES / 2;
        #pragma unroll
        for (int kc = 0; kc < 4; kc++) {
            wmma::fragment<wmma::matrix_a, 16, 16, 16, __half, wmma::row_major> af[2];
            #pragma unroll
            for (int mi = 0; mi < 2; mi++)
                wmma::load_matrix_sync(af[mi], A + (wm * 32 + mi * 16) * A_ROW_H + kc * 16, A_ROW_H);
            #pragma unroll
            for (int ni = 0; ni < 4; ni++) {
                wmma::fragment<wmma::matrix_b, 16, 16, 16, __half, wmma::col_major> bf;
                wmma::load_matrix_sync(bf, B + (wn * 64 + ni * 16) * A_ROW_H + kc * 16, A_ROW_H);
                wmma::mma_sync(acc[0][ni], af[0], bf, acc[0][ni]);
                wmma::mma_sync(acc[1][ni], af[1], bf, acc[1][ni]);
            }
        }
        __syncthreads();
    }

    float* patch = (float*)dyn + warp * 320;
    int rr = lane >> 1;
    int cc0 = (lane & 1) * 8;
    #pragma unroll
    for (int mi = 0; mi < 2; mi++) {
        int gi = i0 + wm * 32 + mi * 16 + rr;
        #pragma unroll
        for (int ni = 0; ni < 4; ni++) {
            wmma::store_matrix_sync(patch, acc[mi][ni], 20, wmma::mem_row_major);
            __syncwarp();
            int nl = wn * 64 + ni * 16 + cc0;
            float* dst = out + (size_t)gi * ODIM + n0 + nl;
            #pragma unroll
            for (int e = 0; e < 8; e++)
                dst[e] = patch[rr * 20 + cc0 + e] + bs[nl + e];
            __syncwarp();
        }
    }
}

// ---------------- launch ----------------
extern "C" void kernel_launch(void* const* d_in, const int* in_sizes, int n_in,
                              void* d_out, int out_size) {
    const float* x = (const float*)d_in[0];
    const float* W = (const float*)d_in[1];
    const float* b = (const float*)d_in[2];
    float* out = (float*)d_out;

    cudaFuncSetAttribute(k_gauss, cudaFuncAttributeMaxDynamicSharedMemorySize, GRAM_DYN);
    cudaFuncSetAttribute(k_pv,    cudaFuncAttributeMaxDynamicSharedMemorySize, PV_DYN);
    cudaFuncSetAttribute(k_head,  cudaFuncAttributeMaxDynamicSharedMemorySize, HEAD_DYN);

    k_prep_x<<<NPTS / 8, 256>>>(x);
    k_prep_w<<<(ODIM * DDIM / 4) / 256, 256>>>(W);
    k_gauss<<<dim3(64, 33), 256, GRAM_DYN>>>();
    k_rowsum<<<NPTS / 256, 256>>>();
    k_pv<<<dim3(DDIM / 128, NPTS / 128), 128, PV_DYN>>>();
    k_head<<<dim3(ODIM / 128, NPTS / 128), 256, HEAD_DYN>>>(b, out);
}

// round 17
// speedup vs baseline: 1.0281x; 1.0281x over previous
#include <cuda_runtime.h>
#include <cuda_fp16.h>
#include <mma.h>
#include <cstdint>

using namespace nvcuda;

#define NPTS 8192
#define DDIM 512
#define ODIM 512

static constexpr float INV2SIG2 = 1.0f / 2048.0f;   // 1/(2*32*32)
static constexpr float EPSV = 1e-8f;

// ---------------- scratch ----------------
__device__ __half g_x[(size_t)NPTS * DDIM];      // fp16 x [N][D]
__device__ __half g_W[(size_t)ODIM * DDIM];      // fp16 W [O][D]
__device__ __half g_P[(size_t)NPTS * NPTS];      // fp16 weights, 128 MB
__device__ __half g_Y[(size_t)NPTS * DDIM];      // fp16 normalized P@x
__device__ float  g_sq[NPTS];
__device__ float  g_invr[NPTS];
__device__ float  g_part[(size_t)64 * NPTS];     // per-sumblock row partials (2 MB)

// ---------------- cp.async ----------------
__device__ __forceinline__ void cp16s(unsigned dst, const void* src) {
    asm volatile("cp.async.cg.shared.global [%0], [%1], 16;" :: "r"(dst), "l"(src));
}
#define CP_COMMIT() asm volatile("cp.async.commit_group;" ::: "memory")
#define CP_WAIT1()  asm volatile("cp.async.wait_group 1;" ::: "memory")
#define CP_WAIT0()  asm volatile("cp.async.wait_group 0;" ::: "memory")

__device__ __forceinline__ unsigned smem_u32(const void* p) {
    return (unsigned)__cvta_generic_to_shared(p);
}

// geometry: BM=128, BN=128, BK=64, 256 thr, 8 warps 4(M)x2(N), warp tile 32x64
#define A_ROW_H   72
#define A_BYTES   18432
#define STAGE_B   36864
#define DYN_SMEM  (2 * STAGE_B)
#define PV_DYN    (3 * STAGE_B)
// gram epilogue aliases inside dyn:
#define TT_OFF    0
#define PATCH_OFF 35840
#define COLP_OFF  46080

// ---------------- K1: merged prep (x convert + norms; W convert) ----------------
__global__ void k_prep(const float* __restrict__ x, const float* __restrict__ W) {
    if (blockIdx.x < NPTS / 8) {
        int row = blockIdx.x * 8 + (threadIdx.x >> 5);
        int lane = threadIdx.x & 31;
        const float4* xr = (const float4*)(x + (size_t)row * DDIM);
        float s = 0.f;
        #pragma unroll
        for (int i = lane; i < 128; i += 32) {
            float4 v = xr[i];
            s += v.x * v.x + v.y * v.y + v.z * v.z + v.w * v.w;
            __half2* dst = (__half2*)(g_x + (size_t)row * DDIM + i * 4);
            dst[0] = __floats2half2_rn(v.x, v.y);
            dst[1] = __floats2half2_rn(v.z, v.w);
        }
        #pragma unroll
        for (int o = 16; o > 0; o >>= 1) s += __shfl_xor_sync(0xffffffff, s, o);
        if (lane == 0) g_sq[row] = s;
    } else {
        int i = (blockIdx.x - NPTS / 8) * blockDim.x + threadIdx.x;   // over float4s (65536)
        float4 v = ((const float4*)W)[i];
        __half2* dst = (__half2*)(g_W + (size_t)i * 4);
        dst[0] = __floats2half2_rn(v.x, v.y);
        dst[1] = __floats2half2_rn(v.z, v.w);
    }
}

// ---------------- K2: symmetric Gram -> exp -> P (both triangles) ----------------
// triangle-packed grid (64 x 33)
__global__ void __launch_bounds__(256) k_gauss() {
    extern __shared__ __align__(16) char dyn[];
    __shared__ float sqj[128];
    __shared__ float part2[2][128];

    int bx = blockIdx.x, by = blockIdx.y;
    int ib, jb;
    if (bx >= by) { ib = by; jb = bx; }
    else {
        if (by == 32) return;
        ib = 64 - by; jb = 63 - bx;
    }
    bool diag = (jb == ib);

    unsigned sb = smem_u32(dyn);
    __half* Hs = (__half*)dyn;

    int i0 = ib * 128;
    int j0 = jb * 128;
    int tid = threadIdx.x, warp = tid >> 5, lane = tid & 31;
    int wm = warp >> 1;   // 0..3
    int wn = warp & 1;    // 0..1

    if (tid < 128) sqj[tid] = g_sq[j0 + tid];

    wmma::fragment<wmma::accumulator, 16, 16, 16, float> acc[2][4];
    #pragma unroll
    for (int a = 0; a < 2; a++)
        #pragma unroll
        for (int b = 0; b < 4; b++) wmma::fill_fragment(acc[a][b], 0.f);

    auto load_chunk = [&](int c, int st) {
        unsigned ab = sb + st * STAGE_B;
        unsigned bb = ab + A_BYTES;
        const __half* ga = g_x + (size_t)i0 * DDIM + c * 64;
        const __half* gb = g_x + (size_t)j0 * DDIM + c * 64;
        #pragma unroll
        for (int q = 0; q < 4; q++) {
            int idx = tid + q * 256;
            int r = idx >> 3, g = idx & 7;
            cp16s(ab + r * 144 + g * 16, ga + (size_t)r * DDIM + g * 8);
        }
        #pragma unroll
        for (int q = 0; q < 4; q++) {
            int idx = tid + q * 256;
            int r = idx >> 3, g = idx & 7;
            cp16s(bb + r * 144 + g * 16, gb + (size_t)r * DDIM + g * 8);
        }
        CP_COMMIT();
    };

    load_chunk(0, 0);
    for (int s = 0; s < 8; s++) {
        int buf = s & 1;
        if (s < 7) { load_chunk(s + 1, buf ^ 1); CP_WAIT1(); } else { CP_WAIT0(); }
        __syncthreads();
        __half* A = Hs + buf * (STAGE_B / 2);
        __half* B = A + A_BYTES / 2;
        #pragma unroll
        for (int kc = 0; kc < 4; kc++) {
            wmma::fragment<wmma::matrix_a, 16, 16, 16, __half, wmma::row_major> af[2];
            #pragma unroll
            for (int mi = 0; mi < 2; mi++)
                wmma::load_matrix_sync(af[mi], A + (wm * 32 + mi * 16) * A_ROW_H + kc * 16, A_ROW_H);
            #pragma unroll
            for (int ni = 0; ni < 4; ni++) {
                wmma::fragment<wmma::matrix_b, 16, 16, 16, __half, wmma::col_major> bf;
                wmma::load_matrix_sync(bf, B + (wn * 64 + ni * 16) * A_ROW_H + kc * 16, A_ROW_H);
                wmma::mma_sync(acc[0][ni], af[0], bf, acc[0][ni]);
                wmma::mma_sync(acc[1][ni], af[1], bf, acc[1][ni]);
            }
        }
        __syncthreads();
    }

    // ---- epilogue ----
    __half* Tt   = (__half*)(dyn + TT_OFF);
    float* patch = (float*)(dyn + PATCH_OFF) + warp * 320;
    float* colp  = (float*)(dyn + COLP_OFF);
    int rr = lane >> 1;
    int cc0 = (lane & 1) * 8;
    float colacc[4][8];
    #pragma unroll
    for (int a = 0; a < 4; a++)
        #pragma unroll
        for (int e = 0; e < 8; e++) colacc[a][e] = 0.f;

    #pragma unroll
    for (int mi = 0; mi < 2; mi++) {
        int row_loc = wm * 32 + mi * 16 + rr;
        int gi = i0 + row_loc;
        float si = g_sq[gi];
        float s = 0.f;
        #pragma unroll
        for (int ni = 0; ni < 4; ni++) {
            wmma::store_matrix_sync(patch, acc[mi][ni], 20, wmma::mem_row_major);
            __syncwarp();
            int jl = wn * 64 + ni * 16 + cc0;
            __half2 buf2[4];
            #pragma unroll
            for (int e = 0; e < 8; e += 2) {
                float d0 = fmaxf(si + sqj[jl + e]     - 2.f * patch[rr * 20 + cc0 + e],     0.f);
                float d1 = fmaxf(si + sqj[jl + e + 1] - 2.f * patch[rr * 20 + cc0 + e + 1], 0.f);
                __half2 hp = __floats2half2_rn(__expf(-d0 * INV2SIG2), __expf(-d1 * INV2SIG2));
                buf2[e >> 1] = hp;
                float2 hf = __half22float2(hp);
                s += hf.x + hf.y;
                if (!diag) {
                    colacc[ni][e]     += hf.x;
                    colacc[ni][e + 1] += hf.y;
                    Tt[(jl + e)     * 136 + row_loc] = __low2half(hp);
                    Tt[(jl + e + 1) * 136 + row_loc] = __high2half(hp);
                }
            }
            *(uint4*)(g_P + (size_t)gi * NPTS + j0 + jl) = *(const uint4*)buf2;
            __syncwarp();
        }
        s += __shfl_xor_sync(0xffffffff, s, 1);
        if ((lane & 1) == 0) part2[wn][row_loc] = s;
    }

    if (!diag) {
        #pragma unroll
        for (int ni = 0; ni < 4; ni++)
            #pragma unroll
            for (int e = 0; e < 8; e++) {
                float v = colacc[ni][e];
                v += __shfl_xor_sync(0xffffffff, v, 2);
                v += __shfl_xor_sync(0xffffffff, v, 4);
                v += __shfl_xor_sync(0xffffffff, v, 8);
                v += __shfl_xor_sync(0xffffffff, v, 16);
                colacc[ni][e] = v;
            }
        if (rr == 0) {
            #pragma unroll
            for (int ni = 0; ni < 4; ni++)
                #pragma unroll
                for (int e = 0; e < 8; e++)
                    colp[wm * 128 + wn * 64 + ni * 16 + cc0 + e] = colacc[ni][e];
        }
    }
    __syncthreads();

    if (tid < 128) {
        g_part[(size_t)jb * NPTS + i0 + tid] = part2[0][tid] + part2[1][tid];
        if (!diag)
            g_part[(size_t)ib * NPTS + j0 + tid] =
                (colp[tid] + colp[128 + tid]) + (colp[256 + tid] + colp[384 + tid]);
    }

    if (!diag) {
        int jc = tid >> 1, ih = tid & 1;
        const uint4* src = (const uint4*)(Tt + jc * 136 + ih * 64);
        uint4* dst = (uint4*)(g_P + (size_t)(j0 + jc) * NPTS + i0 + ih * 64);
        #pragma unroll
        for (int q = 0; q < 8; q++) dst[q] = src[q];
    }
}

// ---------------- K2.5: reduce 64 partials/row -> 1/(sum+eps) ----------------
__global__ void k_rowsum() {
    int row = blockIdx.x * 256 + threadIdx.x;
    float s = 0.f;
    #pragma unroll
    for (int jt = 0; jt < 64; jt++) s += g_part[(size_t)jt * NPTS + row];
    g_invr[row] = 1.f / (s + EPSV);
}

// ---------------- K3: Y = (P @ x) * invr. 128x128 tile, 3-stage single-barrier ----------------
#define PVB_ROW_H 136
__global__ void __launch_bounds__(256) k_pv() {
    extern __shared__ __align__(16) char dyn[];
    unsigned sb = smem_u32(dyn);
    __half* Hs = (__half*)dyn;

    int i0 = blockIdx.y * 128;
    int n0 = blockIdx.x * 128;
    int tid = threadIdx.x, warp = tid >> 5, lane = tid & 31;
    int wm = warp >> 1;
    int wn = warp & 1;

    wmma::fragment<wmma::accumulator, 16, 16, 16, float> acc[2][4];
    #pragma unroll
    for (int a = 0; a < 2; a++)
        #pragma unroll
        for (int b = 0; b < 4; b++) wmma::fill_fragment(acc[a][b], 0.f);

    auto load_chunk = [&](int c, int st) {
        unsigned ab = sb + st * STAGE_B;
        unsigned bb = ab + A_BYTES;
        const __half* ga = g_P + (size_t)i0 * NPTS + c * 64;
        const __half* gb = g_x + (size_t)(c * 64) * DDIM + n0;
        #pragma unroll
        for (int q = 0; q < 4; q++) {
            int idx = tid + q * 256;
            int r = idx >> 3, g = idx & 7;
            cp16s(ab + r * 144 + g * 16, ga + (size_t)r * NPTS + g * 8);
        }
        #pragma unroll
        for (int q = 0; q < 4; q++) {
            int idx = tid + q * 256;
            int r = idx >> 4, g = idx & 15;
            cp16s(bb + r * 272 + g * 16, gb + (size_t)r * DDIM + g * 8);
        }
        CP_COMMIT();
    };

    load_chunk(0, 0);
    load_chunk(1, 1);

    int st = 0;
    for (int s = 0; s < 128; s++) {
        if (s < 127) CP_WAIT1(); else CP_WAIT0();
        __syncthreads();
        if (s + 2 < 128) {
            int st2 = st + 2; if (st2 >= 3) st2 -= 3;
            load_chunk(s + 2, st2);
        }
        __half* A = Hs + st * (STAGE_B / 2);
        __half* B = A + A_BYTES / 2;
        #pragma unroll
        for (int kc = 0; kc < 4; kc++) {
            wmma::fragment<wmma::matrix_a, 16, 16, 16, __half, wmma::row_major> af[2];
            #pragma unroll
            for (int mi = 0; mi < 2; mi++)
                wmma::load_matrix_sync(af[mi], A + (wm * 32 + mi * 16) * A_ROW_H + kc * 16, A_ROW_H);
            #pragma unroll
            for (int ni = 0; ni < 4; ni++) {
                wmma::fragment<wmma::matrix_b, 16, 16, 16, __half, wmma::row_major> bf;
                wmma::load_matrix_sync(bf, B + (kc * 16) * PVB_ROW_H + wn * 64 + ni * 16, PVB_ROW_H);
                wmma::mma_sync(acc[0][ni], af[0], bf, acc[0][ni]);
                wmma::mma_sync(acc[1][ni], af[1], bf, acc[1][ni]);
            }
        }
        if (++st >= 3) st = 0;
    }

    float* patch = (float*)dyn + warp * 320;
    int rr = lane >> 1;
    int cc0 = (lane & 1) * 8;
    #pragma unroll
    for (int mi = 0; mi < 2; mi++) {
        int gi = i0 + wm * 32 + mi * 16 + rr;
        float inv = g_invr[gi];
        #pragma unroll
        for (int ni = 0; ni < 4; ni++) {
            wmma::store_matrix_sync(patch, acc[mi][ni], 20, wmma::mem_row_major);
            __syncwarp();
            int nl = wn * 64 + ni * 16 + cc0;
            __half2 buf2[4];
            #pragma unroll
            for (int e = 0; e < 8; e += 2)
                buf2[e >> 1] = __floats2half2_rn(patch[rr * 20 + cc0 + e] * inv,
                                                 patch[rr * 20 + cc0 + e + 1] * inv);
            *(uint4*)(g_Y + (size_t)gi * DDIM + n0 + nl) = *(const uint4*)buf2;
            __syncwarp();
        }
    }
}

// ---------------- K4: out = Y @ W^T + b. 128x128 tile, K=512 ----------------
__global__ void __launch_bounds__(256) k_head(const float* __restrict__ bvec,
                                              float* __restrict__ out) {
    extern __shared__ __align__(16) char dyn[];
    __shared__ float bs[128];
    unsigned sb = smem_u32(dyn);
    __half* Hs = (__half*)dyn;

    int i0 = blockIdx.y * 128;
    int n0 = blockIdx.x * 128;
    int tid = threadIdx.x, warp = tid >> 5, lane = tid & 31;
    int wm = warp >> 1;
    int wn = warp & 1;

    if (tid < 128) bs[tid] = bvec[n0 + tid];

    wmma::fragment<wmma::accumulator, 16, 16, 16, float> acc[2][4];
    #pragma unroll
    for (int a = 0; a < 2; a++)
        #pragma unroll
        for (int b = 0; b < 4; b++) wmma::fill_fragment(acc[a][b], 0.f);

    auto load_chunk = [&](int c, int st) {
        unsigned ab = sb + st * STAGE_B;
        unsigned bb = ab + A_BYTES;
        const __half* ga = g_Y + (size_t)i0 * DDIM + c * 64;
        const __half* gb = g_W + (size_t)n0 * DDIM + c * 64;
        #pragma unroll
        for (int q = 0; q < 4; q++) {
            int idx = tid + q * 256;
            int r = idx >> 3, g = idx & 7;
            cp16s(ab + r * 144 + g * 16, ga + (size_t)r * DDIM + g * 8);
        }
        #pragma unroll
        for (int q = 0; q < 4; q++) {
            int idx = tid + q * 256;
            int r = idx >> 3, g = idx & 7;
            cp16s(bb + r * 144 + g * 16, gb + (size_t)r * DDIM + g * 8);
        }
        CP_COMMIT();
    };

    load_chunk(0, 0);
    for (int s = 0; s < 8; s++) {
        int buf = s & 1;
        if (s < 7) { load_chunk(s + 1, buf ^ 1); CP_WAIT1(); } else { CP_WAIT0(); }
        __syncthreads();
        __half* A = Hs + buf * (STAGE_B / 2);
        __half* B = A + A_BYTES / 2;
        #pragma unroll
        for (int kc = 0; kc < 4; kc++) {
            wmma::fragment<wmma::matrix_a, 16, 16, 16, __half, wmma::row_major> af[2];
            #pragma unroll
            for (int mi = 0; mi < 2; mi++)
                wmma::load_matrix_sync(af[mi], A + (wm * 32 + mi * 16) * A_ROW_H + kc * 16, A_ROW_H);
            #pragma unroll
            for (int ni = 0; ni < 4; ni++) {
                wmma::fragment<wmma::matrix_b, 16, 16, 16, __half, wmma::col_major> bf;
                wmma::load_matrix_sync(bf, B + (wn * 64 + ni * 16) * A_ROW_H + kc * 16, A_ROW_H);
                wmma::mma_sync(acc[0][ni], af[0], bf, acc[0][ni]);
                wmma::mma_sync(acc[1][ni], af[1], bf, acc[1][ni]);
            }
        }
        __syncthreads();
    }

    float* patch = (float*)dyn + warp * 320;
    int rr = lane >> 1;
    int cc0 = (lane & 1) * 8;
    #pragma unroll
    for (int mi = 0; mi < 2; mi++) {
        int gi = i0 + wm * 32 + mi * 16 + rr;
        #pragma unroll
        for (int ni = 0; ni < 4; ni++) {
            wmma::store_matrix_sync(patch, acc[mi][ni], 20, wmma::mem_row_major);
            __syncwarp();
            int nl = wn * 64 + ni * 16 + cc0;
            float* dst = out + (size_t)gi * ODIM + n0 + nl;
            #pragma unroll
            for (int e = 0; e < 8; e++)
                dst[e] = patch[rr * 20 + cc0 + e] + bs[nl + e];
            __syncwarp();
        }
    }
}

// ---------------- launch ----------------
extern "C" void kernel_launch(void* const* d_in, const int* in_sizes, int n_in,
                              void* d_out, int out_size) {
    const float* x = (const float*)d_in[0];
    const float* W = (const float*)d_in[1];
    const float* b = (const float*)d_in[2];
    float* out = (float*)d_out;

    cudaFuncSetAttribute(k_gauss, cudaFuncAttributeMaxDynamicSharedMemorySize, DYN_SMEM);
    cudaFuncSetAttribute(k_pv,    cudaFuncAttributeMaxDynamicSharedMemorySize, PV_DYN);
    cudaFuncSetAttribute(k_head,  cudaFuncAttributeMaxDynamicSharedMemorySize, DYN_SMEM);

    k_prep<<<NPTS / 8 + (ODIM * DDIM / 4) / 256, 256>>>(x, W);
    k_gauss<<<dim3(64, 33), 256, DYN_SMEM>>>();
    k_rowsum<<<NPTS / 256, 256>>>();
    k_pv<<<dim3(DDIM / 128, NPTS / 128), 256, PV_DYN>>>();
    k_head<<<dim3(ODIM / 128, NPTS / 128), 256, DYN_SMEM>>>(b, out);
}